// round 14
// baseline (speedup 1.0000x reference)
#include <cuda_runtime.h>
#include <cuda_bf16.h>
#include <math.h>
#include <stdint.h>

#define B_    4
#define T_    4096
#define D_    1024
#define H_    16
#define R_    32
#define DH_   64
#define BH_   64
#define MROWS 16384
#define NCH   16
#define ZK    512              // Z feature dim (H_*R_)

// ---- mma.sync GEMM tiling ----
#define BM 128
#define BN 128
#define BK 32
#define ST_A_H 0
#define ST_A_L (8*1024)
#define ST_B_H (16*1024)
#define ST_B_L (24*1024)
#define STAGE  (32*1024)
#define NSTAGE 3
#define GEMM_SMEM (NSTAGE*STAGE)

// ---------------- scratch (device globals; no allocation) ----------------
__device__ __align__(128) __nv_bfloat16 g_Ah[(size_t)MROWS * D_];
__device__ __align__(128) __nv_bfloat16 g_Al[(size_t)MROWS * D_];
__device__ __align__(128) __nv_bfloat16 g_Wth[(size_t)2048 * D_];   // [n][k] KQV bf16 hi
__device__ __align__(128) __nv_bfloat16 g_Wtl[(size_t)2048 * D_];   // [n][k] KQV bf16 lo
__device__ __align__(128) __nv_bfloat16 g_Zh[(size_t)MROWS * ZK];   // token z hi
__device__ __align__(128) __nv_bfloat16 g_Zl[(size_t)MROWS * ZK];   // token z lo
__device__ __align__(128) __nv_bfloat16 g_W2h[(size_t)B_ * 1024 * ZK]; // [b][n][k] hi
__device__ __align__(128) __nv_bfloat16 g_W2l[(size_t)B_ * 1024 * ZK]; // [b][n][k] lo
__device__ float g_K[(size_t)BH_ * T_ * R_];
__device__ float g_V[(size_t)BH_ * T_ * DH_];
__device__ float g_part[(size_t)BH_ * NCH * 4096];
__device__ float g_Tmat[(size_t)BH_ * DH_ * R_];

// ---------------- PTX helpers (baseline ISA only) ----------------
__device__ __forceinline__ uint32_t smem_u32(const void* p) {
    uint32_t a;
    asm("{ .reg .u64 t; cvta.to.shared.u64 t, %1; cvt.u32.u64 %0, t; }" : "=r"(a) : "l"(p));
    return a;
}
__device__ __forceinline__ void cp16(uint32_t dst, const void* src) {
    asm volatile("cp.async.cg.shared.global [%0], [%1], 16;" :: "r"(dst), "l"(src) : "memory");
}
__device__ __forceinline__ void cp_commit() {
    asm volatile("cp.async.commit_group;" ::: "memory");
}
template<int N> __device__ __forceinline__ void cp_wait() {
    asm volatile("cp.async.wait_group %0;" :: "n"(N) : "memory");
}
__device__ __forceinline__ void ldsm4(uint32_t* r, uint32_t addr) {
    asm volatile("ldmatrix.sync.aligned.m8n8.x4.shared.b16 {%0,%1,%2,%3}, [%4];"
                 : "=r"(r[0]), "=r"(r[1]), "=r"(r[2]), "=r"(r[3]) : "r"(addr));
}
__device__ __forceinline__ void mma16816(float* c, const uint32_t* a, const uint32_t* b) {
    asm volatile("mma.sync.aligned.m16n8k16.row.col.f32.bf16.bf16.f32 "
                 "{%0,%1,%2,%3}, {%4,%5,%6,%7}, {%8,%9}, {%0,%1,%2,%3};"
                 : "+f"(c[0]), "+f"(c[1]), "+f"(c[2]), "+f"(c[3])
                 : "r"(a[0]), "r"(a[1]), "r"(a[2]), "r"(a[3]), "r"(b[0]), "r"(b[1]));
}
// packed f32x2 FMA (sm_100+ family): d = a*b + d, lanewise IEEE fp32
__device__ __forceinline__ void ffma2(unsigned long long& d, unsigned long long a,
                                      unsigned long long b) {
    asm("fma.rn.f32x2 %0, %1, %2, %0;" : "+l"(d) : "l"(a), "l"(b));
}
__device__ __forceinline__ unsigned long long pack2(float x) {
    unsigned long long d;
    asm("mov.b64 %0, {%1, %2};" : "=l"(d) : "f"(x), "f"(x));
    return d;
}
__device__ __forceinline__ void unpack2(unsigned long long v, float& lo, float& hi) {
    asm("mov.b64 {%0, %1}, %2;" : "=f"(lo), "=f"(hi) : "l"(v));
}
// 64B-row swizzle
__device__ __forceinline__ uint32_t swz64(uint32_t b) { return b ^ ((b >> 3) & 0x30); }

// ---------------- LayerNorm -> bf16 hi/lo ----------------
__global__ __launch_bounds__(256)
void ln_split_kernel(const float* __restrict__ x, const float* __restrict__ sc,
                     const float* __restrict__ bi)
{
    int row = blockIdx.x;
    int tid = threadIdx.x;
    const float4* xr = (const float4*)(x + (size_t)row * D_);
    float4 v = xr[tid];
    float s  = v.x + v.y + v.z + v.w;
    float ss = v.x*v.x + v.y*v.y + v.z*v.z + v.w*v.w;
    __shared__ float rs[8], rss[8];
    #pragma unroll
    for (int o = 16; o > 0; o >>= 1) {
        s  += __shfl_down_sync(0xffffffffu, s,  o);
        ss += __shfl_down_sync(0xffffffffu, ss, o);
    }
    int w = tid >> 5, l = tid & 31;
    if (l == 0) { rs[w] = s; rss[w] = ss; }
    __syncthreads();
    if (tid == 0) {
        float a = 0.f, b = 0.f;
        #pragma unroll
        for (int i = 0; i < 8; i++) { a += rs[i]; b += rss[i]; }
        rs[0] = a; rss[0] = b;
    }
    __syncthreads();
    float mu   = rs[0]  * (1.0f / D_);
    float var  = rss[0] * (1.0f / D_) - mu * mu;
    float rstd = rsqrtf(var + 1e-5f);
    float4 s4 = ((const float4*)sc)[tid];
    float4 b4 = ((const float4*)bi)[tid];
    float o0 = (v.x - mu) * rstd * s4.x + b4.x;
    float o1 = (v.y - mu) * rstd * s4.y + b4.y;
    float o2 = (v.z - mu) * rstd * s4.z + b4.z;
    float o3 = (v.w - mu) * rstd * s4.w + b4.w;
    size_t base = (size_t)row * D_ + tid * 4;
    __nv_bfloat162 h01, h23, l01, l23;
    h01.x = __float2bfloat16(o0); h01.y = __float2bfloat16(o1);
    h23.x = __float2bfloat16(o2); h23.y = __float2bfloat16(o3);
    l01.x = __float2bfloat16(o0 - __bfloat162float(h01.x));
    l01.y = __float2bfloat16(o1 - __bfloat162float(h01.y));
    l23.x = __float2bfloat16(o2 - __bfloat162float(h23.x));
    l23.y = __float2bfloat16(o3 - __bfloat162float(h23.y));
    *(__nv_bfloat162*)(g_Ah + base)     = h01;
    *(__nv_bfloat162*)(g_Ah + base + 2) = h23;
    *(__nv_bfloat162*)(g_Al + base)     = l01;
    *(__nv_bfloat162*)(g_Al + base + 2) = l23;
}

// ---------------- weight transpose + split (Wk/Wq/Wv) ----------------
__global__ __launch_bounds__(256)
void trans_split_kernel(const float* __restrict__ Wk, const float* __restrict__ Wq,
                        const float* __restrict__ Wv)
{
    __shared__ float tile[32][33];
    int z = blockIdx.z;
    const float* W;
    __nv_bfloat16 *dh, *dl;
    int N;
    if (z == 0)      { W = Wk; N = 512;  dh = g_Wth;  dl = g_Wtl; }
    else if (z == 1) { W = Wq; N = 512;  dh = g_Wth + 512 * 1024;  dl = g_Wtl + 512 * 1024; }
    else             { W = Wv; N = 1024; dh = g_Wth + 1024 * 1024; dl = g_Wtl + 1024 * 1024; }
    int n0 = blockIdx.x * 32, k0 = blockIdx.y * 32;
    if (n0 >= N) return;
    int lane = threadIdx.x & 31, wrp = threadIdx.x >> 5;
    for (int i = wrp; i < 32; i += 8)
        tile[i][lane] = W[(size_t)(k0 + i) * N + n0 + lane];
    __syncthreads();
    for (int i = wrp; i < 32; i += 8) {
        float v = tile[lane][i];
        __nv_bfloat16 h = __float2bfloat16(v);
        dh[(size_t)(n0 + i) * D_ + k0 + lane] = h;
        dl[(size_t)(n0 + i) * D_ + k0 + lane] = __float2bfloat16(v - __bfloat162float(h));
    }
}

// ---------------- split-bf16 mma.sync GEMM (templated on mode) ----------------
// MODE 0: A=g_Ah/Al [16384][1024], B=g_Wth/Wtl [2048][1024]
//         skips dead tiles (K & V for t>=P, Q for t<P); epilogue: g_K, g_V, Z
// MODE 1: A=g_Zh/Zl [16384][512],  B=g_W2h/W2l (per-batch), out = sigmoid(gate)*C
template<int MODE>
__global__ __launch_bounds__(256, 2)
void mma_gemm_kernel(float* __restrict__ Cout, const float* __restrict__ gate,
                     const int* __restrict__ pl)
{
    extern __shared__ __align__(1024) char sm[];
    uint32_t sbase = smem_u32(sm);

    const int tid  = threadIdx.x;
    const int lane = tid & 31;
    const int wid  = tid >> 5;
    const int wm   = wid & 3;        // m block (32 rows)
    const int wn   = wid >> 2;       // n block (64 cols)
    const int m0   = blockIdx.y * BM;
    const int ntb  = blockIdx.x * BN;

    int P = *pl; if (P < 1) P = 1; if (P > T_ - 1) P = T_ - 1;

    if (MODE == 0) {
        int t0 = m0 & (T_ - 1);             // BM=128 rows share one batch
        if (ntb < 512) {                    // K region: only t < P read
            if (t0 >= P) return;
        } else if (ntb < 1024) {            // Q region: only t >= P read
            if (t0 + BM - 1 < P) return;
        } else {                            // V region: only t < P read
            if (t0 >= P) return;
        }
    }

    const __nv_bfloat16* Agh;
    const __nv_bfloat16* Agl;
    const __nv_bfloat16* Bgh;
    const __nv_bfloat16* Bgl;
    constexpr int lda = (MODE == 0) ? D_ : ZK;
    constexpr int kch = lda / BK;
    if (MODE == 0) {
        Agh = g_Ah; Agl = g_Al; Bgh = g_Wth; Bgl = g_Wtl;
    } else {
        size_t boff = (size_t)(m0 >> 12) * 1024 * ZK;
        Agh = g_Zh; Agl = g_Zl; Bgh = g_W2h + boff; Bgl = g_W2l + boff;
    }

    float acc[2][8][4];
    #pragma unroll
    for (int i = 0; i < 2; i++)
        #pragma unroll
        for (int j = 0; j < 8; j++)
            #pragma unroll
            for (int k = 0; k < 4; k++) acc[i][j][k] = 0.f;

    const int a_r15 = lane & 15;
    const int a_hi  = lane >> 4;
    const int b_nr  = (lane & 7) | ((lane >> 1) & 8);
    const int b_hi  = (lane >> 3) & 1;

    // loader: 512 16B-units per tensor, 2 per thread
    #define LOAD_STAGE(stg, koff)                                              \
        do {                                                                   \
            _Pragma("unroll")                                                  \
            for (int i_ = 0; i_ < 2; i_++) {                                   \
                int idx_ = tid + i_ * 256;                                     \
                int row_ = idx_ >> 2, u_ = idx_ & 3;                           \
                uint32_t d_ = swz64(row_ * 64 + u_ * 16);                      \
                size_t ka_ = (size_t)(m0 + row_) * lda + (koff) + u_ * 8;      \
                size_t kb_ = (size_t)(ntb + row_) * lda + (koff) + u_ * 8;     \
                cp16((stg) + ST_A_H + d_, Agh + ka_);                          \
                cp16((stg) + ST_A_L + d_, Agl + ka_);                          \
                cp16((stg) + ST_B_H + d_, Bgh + kb_);                          \
                cp16((stg) + ST_B_L + d_, Bgl + kb_);                          \
            }                                                                  \
            cp_commit();                                                       \
        } while (0)

    LOAD_STAGE(sbase, 0);
    LOAD_STAGE(sbase + STAGE, BK);

    int snext = 2;                 // stage receiving prefetch (issued post-sync)
    int scur  = 0;                 // stage being consumed
    for (int c = 0; c < kch; c++) {
        if (c + 1 < kch) cp_wait<1>(); else cp_wait<0>();
        __syncthreads();           // all warps done reading stage snext's old data
        if (c + 2 < kch) LOAD_STAGE(sbase + snext * STAGE, (c + 2) * BK);

        uint32_t st = sbase + scur * STAGE;
        #pragma unroll
        for (int ks = 0; ks < 2; ks++) {
            uint32_t ah0[4], ah1[4], al0[4], al1[4];
            {
                int u = ks * 2 + a_hi;
                uint32_t off0 = swz64((wm * 32 + a_r15) * 64 + u * 16);
                uint32_t off1 = swz64((wm * 32 + 16 + a_r15) * 64 + u * 16);
                ldsm4(ah0, st + ST_A_H + off0);
                ldsm4(ah1, st + ST_A_H + off1);
                ldsm4(al0, st + ST_A_L + off0);
                ldsm4(al1, st + ST_A_L + off1);
            }
            #pragma unroll
            for (int half = 0; half < 2; half++) {
                uint32_t bh[4][2], bl[4][2];
                #pragma unroll
                for (int p = 0; p < 2; p++) {
                    int u = ks * 2 + b_hi;
                    uint32_t off = swz64((wn * 64 + half * 32 + p * 16 + b_nr) * 64 + u * 16);
                    uint32_t r[4];
                    ldsm4(r, st + ST_B_H + off);
                    bh[p*2][0] = r[0]; bh[p*2][1] = r[1];
                    bh[p*2+1][0] = r[2]; bh[p*2+1][1] = r[3];
                    ldsm4(r, st + ST_B_L + off);
                    bl[p*2][0] = r[0]; bl[p*2][1] = r[1];
                    bl[p*2+1][0] = r[2]; bl[p*2+1][1] = r[3];
                }
                #pragma unroll
                for (int f = 0; f < 4; f++) {
                    int nf = half * 4 + f;
                    mma16816(acc[0][nf], ah0, bh[f]);
                    mma16816(acc[1][nf], ah1, bh[f]);
                    mma16816(acc[0][nf], ah0, bl[f]);
                    mma16816(acc[1][nf], ah1, bl[f]);
                    mma16816(acc[0][nf], al0, bh[f]);
                    mma16816(acc[1][nf], al1, bh[f]);
                }
            }
        }
        scur  = (scur == NSTAGE - 1) ? 0 : scur + 1;
        snext = (snext == NSTAGE - 1) ? 0 : snext + 1;
    }

    // ---- epilogue ----
    float gm = (MODE == 1) ? (1.0f / (1.0f + expf(-gate[0]))) : 1.0f;
    #pragma unroll
    for (int mf = 0; mf < 2; mf++) {
        int mrow0 = m0 + wm * 32 + mf * 16 + (lane >> 2);
        #pragma unroll
        for (int nf = 0; nf < 8; nf++) {
            int n = ntb + wn * 64 + nf * 8 + (lane & 3) * 2;
            #pragma unroll
            for (int rh = 0; rh < 2; rh++) {
                int m = mrow0 + rh * 8;
                float2 v;
                v.x = gm * acc[mf][nf][rh * 2 + 0];
                v.y = gm * acc[mf][nf][rh * 2 + 1];
                if (MODE == 1) {
                    *(float2*)(Cout + (size_t)m * 1024 + n) = v;
                } else {
                    int b = m >> 12, t = m & (T_ - 1);
                    if (n < 1024) {
                        int zc = (n < 512) ? n : (n - 512);
                        bool emit = (n < 512) ? (t < P) : (t >= P);
                        if (emit) {
                            __nv_bfloat162 hv, lv;
                            hv.x = __float2bfloat16(v.x);
                            hv.y = __float2bfloat16(v.y);
                            lv.x = __float2bfloat16(v.x - __bfloat162float(hv.x));
                            lv.y = __float2bfloat16(v.y - __bfloat162float(hv.y));
                            *(__nv_bfloat162*)(g_Zh + (size_t)m * ZK + zc) = hv;
                            *(__nv_bfloat162*)(g_Zl + (size_t)m * ZK + zc) = lv;
                        }
                        if (n < 512) {
                            float* dst = g_K + (((size_t)(b * H_ + (n >> 5))) * T_ + t) * R_ + (n & 31);
                            *(float2*)dst = v;
                        }
                    } else {
                        int nv = n - 1024;
                        float* dst = g_V + (((size_t)(b * H_ + (nv >> 6))) * T_ + t) * DH_ + (nv & 63);
                        *(float2*)dst = v;
                    }
                }
            }
        }
    }
}

// ---------------- partial G/M/Cv accumulation (packed f32x2 FMA) ----------------
__global__ __launch_bounds__(256)
void build_partial_kernel(const int* __restrict__ pl)
{
    int bh = blockIdx.x;
    int chunk = blockIdx.y;
    int P = *pl; if (P < 1) P = 1; if (P > T_ - 1) P = T_ - 1;
    int ch = (P + NCH - 1) / NCH;
    int lo = chunk * ch;
    int hi = min(lo + ch, P);
    int Pm1 = P - 1;

    const float* K = g_K + (size_t)bh * T_ * R_;
    const float* V = g_V + (size_t)bh * T_ * DH_;
    __shared__ __align__(16) float Ks[65][32];
    __shared__ __align__(16) float Vs[64][64];

    int tid = threadIdx.x;
    int r = tid & 31, g = tid >> 5;
    unsigned long long gacc01 = 0, gacc23 = 0;
    unsigned long long macc01 = 0, macc23 = 0;
    unsigned long long ca01 = 0, ca23 = 0;
    unsigned long long cb01 = 0, cb23 = 0;

    for (int t0 = lo; t0 < hi; t0 += 64) {
        int nrows = min(64, hi - t0);
        for (int idx = tid; idx < (nrows + 1) * 8; idx += 256) {
            int rr = idx >> 3, cq = (idx & 7) * 4;
            *(float4*)&Ks[rr][cq] = *(const float4*)&K[(size_t)(t0 + rr) * R_ + cq];
        }
        for (int idx = tid; idx < nrows * 16; idx += 256) {
            int rr = idx >> 4, cq = (idx & 15) * 4;
            *(float4*)&Vs[rr][cq] = *(const float4*)&V[(size_t)(t0 + rr) * DH_ + cq];
        }
        __syncthreads();
        #pragma unroll 4
        for (int tt = 0; tt < nrows; tt++) {
            float kr = Ks[tt][r];
            float kn = (t0 + tt < Pm1) ? Ks[tt + 1][r] : 0.f;
            unsigned long long kr2 = pack2(kr);
            unsigned long long kn2 = pack2(kn);
            unsigned long long ks01 = *(const unsigned long long*)&Ks[tt][g * 4];
            unsigned long long ks23 = *(const unsigned long long*)&Ks[tt][g * 4 + 2];
            unsigned long long va01 = *(const unsigned long long*)&Vs[tt][g * 8];
            unsigned long long va23 = *(const unsigned long long*)&Vs[tt][g * 8 + 2];
            unsigned long long vb01 = *(const unsigned long long*)&Vs[tt][g * 8 + 4];
            unsigned long long vb23 = *(const unsigned long long*)&Vs[tt][g * 8 + 6];
            ffma2(gacc01, kr2, ks01);
            ffma2(gacc23, kr2, ks23);
            ffma2(macc01, kn2, ks01);
            ffma2(macc23, kn2, ks23);
            ffma2(ca01, kr2, va01);
            ffma2(ca23, kr2, va23);
            ffma2(cb01, kr2, vb01);
            ffma2(cb23, kr2, vb23);
        }
        __syncthreads();
    }
    float ge[4], me[4], ce[8];
    unpack2(gacc01, ge[0], ge[1]); unpack2(gacc23, ge[2], ge[3]);
    unpack2(macc01, me[0], me[1]); unpack2(macc23, me[2], me[3]);
    unpack2(ca01, ce[0], ce[1]); unpack2(ca23, ce[2], ce[3]);
    unpack2(cb01, ce[4], ce[5]); unpack2(cb23, ce[6], ce[7]);

    float* out = g_part + ((size_t)bh * NCH + chunk) * 4096;
    #pragma unroll
    for (int j = 0; j < 4; j++) {
        out[r * 32 + g * 4 + j]        = ge[j];
        out[1024 + r * 32 + g * 4 + j] = me[j];
    }
    #pragma unroll
    for (int j = 0; j < 8; j++)
        out[2048 + (g * 8 + j) * 32 + r] = ce[j];
}

// ---------------- per-head solve ----------------
#define MM32(Cm, Am, Bm)                                                     \
    do {                                                                     \
        for (int e = tid; e < 1024; e += 256) {                              \
            int rr = e >> 5, cc = e & 31; float s = 0.f;                     \
            _Pragma("unroll") for (int k2 = 0; k2 < 32; k2++)                \
                s += Am[rr][k2] * Bm[k2][cc];                                \
            Cm[rr][cc] = s;                                                  \
        }                                                                    \
        __syncthreads();                                                     \
    } while (0)

__global__ __launch_bounds__(256)
void solve_kernel(const float* __restrict__ lridge, const float* __restrict__ lgamma)
{
    __shared__ float sG[32][33], sM[32][33], sL[32][33], sLi[32][33];
    __shared__ float sAw[32][33], sT[32][33];
    __shared__ float sCv[64][33], sBv[64][33];
    __shared__ float sScale;

    int bh = blockIdx.x;
    int tid = threadIdx.x;

    // float4 reduce of NCH partials
    const float* base = g_part + (size_t)bh * NCH * 4096;
    for (int idx4 = tid; idx4 < 1024; idx4 += 256) {
        float4 s = {0.f, 0.f, 0.f, 0.f};
        #pragma unroll
        for (int c = 0; c < NCH; c++) {
            float4 p = *(const float4*)&base[(size_t)c * 4096 + idx4 * 4];
            s.x += p.x; s.y += p.y; s.z += p.z; s.w += p.w;
        }
        int idx = idx4 * 4;
        #pragma unroll
        for (int j = 0; j < 4; j++) {
            float sv = (&s.x)[j];
            int e = idx + j;
            if (e < 1024)      sG[e >> 5][e & 31] = sv;
            else if (e < 2048) sM[(e - 1024) >> 5][e & 31] = sv;
            else { int e2 = e - 2048; sCv[e2 >> 5][e2 & 31] = sv; }
        }
    }
    __syncthreads();
    if (tid < 32) sG[tid][tid] += expf(lridge[0]);
    __syncthreads();

    if (tid < 32) {
        int i = tid;
        for (int j = 0; j < 32; j++) {
            if (i == j) {
                float s = sG[j][j];
                for (int k = 0; k < j; k++) s -= sL[j][k] * sL[j][k];
                sL[j][j] = sqrtf(fmaxf(s, 1e-30f));
            }
            __syncwarp();
            if (i > j) {
                float s = sG[i][j];
                for (int k = 0; k < j; k++) s -= sL[i][k] * sL[j][k];
                sL[i][j] = s / sL[j][j];
            } else if (i < j) {
                sL[i][j] = 0.f;
            }
            __syncwarp();
        }
        int j = tid;
        for (int i2 = 0; i2 < 32; i2++) sLi[i2][j] = 0.f;
        for (int i2 = j; i2 < 32; i2++) {
            float s = (i2 == j) ? 1.f : 0.f;
            for (int k = j; k < i2; k++) s -= sL[i2][k] * sLi[k][j];
            sLi[i2][j] = s / sL[i2][i2];
        }
    }
    __syncthreads();

    MM32(sT, sLi, sM);
    for (int e = tid; e < 1024; e += 256) {
        int rr = e >> 5, cc = e & 31; float s = 0.f;
        #pragma unroll
        for (int k2 = 0; k2 < 32; k2++) s += sT[rr][k2] * sLi[cc][k2];
        sAw[rr][cc] = s;
    }
    __syncthreads();

    if (tid < 32) {
        int i = tid;
        float v = 1.0f + 0.37f * (float)i;
        float sig = 0.f;
        for (int it = 0; it < 64; it++) {
            float u = 0.f;
            #pragma unroll
            for (int k = 0; k < 32; k++) u += sAw[i][k] * __shfl_sync(0xffffffffu, v, k);
            float w = 0.f;
            #pragma unroll
            for (int k = 0; k < 32; k++) w += sAw[k][i] * __shfl_sync(0xffffffffu, u, k);
            float n2 = w * w;
            #pragma unroll
            for (int o = 16; o > 0; o >>= 1) n2 += __shfl_xor_sync(0xffffffffu, n2, o);
            float nrm = sqrtf(n2);
            v = w / fmaxf(nrm, 1e-30f);
            sig = sqrtf(nrm);
        }
        if (i == 0) {
            float gamma = expf(lgamma[0]);
            float gc = fminf(gamma, 1.0f);
            float s0 = fmaxf(sig, 1e-8f);
            sScale = gc / fmaxf(s0, 1.0f);
        }
    }
    __syncthreads();
    float scl = sScale;
    for (int e = tid; e < 1024; e += 256) sAw[e >> 5][e & 31] *= scl;
    __syncthreads();

    MM32(sT, sAw, sAw);
    MM32(sM, sT, sT);
    MM32(sG, sM, sLi);
    MM32(sT, sL, sG);

    for (int e = tid; e < 2048; e += 256) {
        int dd = e >> 5, rr = e & 31; float s = 0.f;
        #pragma unroll
        for (int k2 = 0; k2 < 32; k2++) s += sCv[dd][k2] * sLi[rr][k2];
        sBv[dd][rr] = s;
    }
    __syncthreads();
    for (int e = tid; e < 2048; e += 256) {
        int dd = e >> 5, rr = e & 31; float s = 0.f;
        #pragma unroll
        for (int k2 = 0; k2 < 32; k2++) s += sBv[dd][k2] * sLi[k2][rr];
        sCv[dd][rr] = s;
    }
    __syncthreads();

    float* tm = g_Tmat + (size_t)bh * DH_ * R_;
    for (int e = tid; e < 2048; e += 256) {
        int dd = e >> 5, rr = e & 31; float s = 0.f;
        #pragma unroll
        for (int k2 = 0; k2 < 32; k2++) s += sCv[dd][k2] * sT[k2][rr];
        tm[dd * R_ + rr] = s;
    }
}

// ---------------- W2_b[n][h*32+r] = sum_d Tmat_bh[d][r] * Wo[h*64+d][n] (fp32 Wo) ----------------
__global__ __launch_bounds__(256)
void w2_kernel(const float* __restrict__ Wo)
{
    int bh = blockIdx.x;            // b*16+h
    int h  = bh & 15;
    int b  = bh >> 4;
    int n  = blockIdx.y * 256 + threadIdx.x;   // output column 0..1023

    __shared__ float Tm[DH_][R_ + 1];
    for (int i = threadIdx.x; i < DH_ * R_; i += 256)
        Tm[i >> 5][i & 31] = g_Tmat[(size_t)bh * DH_ * R_ + i];
    __syncthreads();

    float s[R_];
    #pragma unroll
    for (int r = 0; r < R_; r++) s[r] = 0.f;
    for (int d = 0; d < DH_; d++) {
        float w = Wo[(size_t)(h * DH_ + d) * 1024 + n];   // coalesced over n
        #pragma unroll
        for (int r = 0; r < R_; r++) s[r] += Tm[d][r] * w;
    }
    size_t base = ((size_t)b * 1024 + n) * ZK + h * R_;
    #pragma unroll
    for (int r = 0; r < R_; r++) {
        __nv_bfloat16 hv = __float2bfloat16(s[r]);
        g_W2h[base + r] = hv;
        g_W2l[base + r] = __float2bfloat16(s[r] - __bfloat162float(hv));
    }
}

// ---------------- launcher ----------------
extern "C" void kernel_launch(void* const* d_in, const int* in_sizes, int n_in,
                              void* d_out, int out_size)
{
    const float* hs     = (const float*)d_in[0];
    const float* Wk     = (const float*)d_in[1];
    const float* Wq     = (const float*)d_in[2];
    const float* Wv     = (const float*)d_in[3];
    const float* Wo     = (const float*)d_in[4];
    const float* lns    = (const float*)d_in[5];
    const float* lnb    = (const float*)d_in[6];
    const float* gate   = (const float*)d_in[7];
    const float* lridge = (const float*)d_in[8];
    const float* lgamma = (const float*)d_in[9];
    const int*   pl     = (const int*)d_in[10];
    float* out = (float*)d_out;

    cudaFuncSetAttribute(mma_gemm_kernel<0>,
                         cudaFuncAttributeMaxDynamicSharedMemorySize, GEMM_SMEM);
    cudaFuncSetAttribute(mma_gemm_kernel<1>,
                         cudaFuncAttributeMaxDynamicSharedMemorySize, GEMM_SMEM);

    ln_split_kernel<<<MROWS, 256>>>(hs, lns, lnb);

    trans_split_kernel<<<dim3(32, 32, 3), 256>>>(Wk, Wq, Wv);

    mma_gemm_kernel<0><<<dim3(2048 / BN, MROWS / BM), 256, GEMM_SMEM>>>(nullptr, nullptr, pl);

    build_partial_kernel<<<dim3(BH_, NCH), 256>>>(pl);
    solve_kernel<<<BH_, 256>>>(lridge, lgamma);
    w2_kernel<<<dim3(BH_, 4), 256>>>(Wo);

    mma_gemm_kernel<1><<<dim3(1024 / BN, MROWS / BM), 256, GEMM_SMEM>>>(out, gate, pl);
}

// round 15
// speedup vs baseline: 1.0114x; 1.0114x over previous
#include <cuda_runtime.h>
#include <cuda_bf16.h>
#include <math.h>
#include <stdint.h>

#define B_    4
#define T_    4096
#define D_    1024
#define H_    16
#define R_    32
#define DH_   64
#define BH_   64
#define MROWS 16384
#define NCH   16
#define ZK    512              // Z feature dim (H_*R_)

// ---- mma.sync GEMM tiling ----
#define BM 128
#define BN 128
#define BK 32
#define ST_A_H 0
#define ST_A_L (8*1024)
#define ST_B_H (16*1024)
#define ST_B_L (24*1024)
#define STAGE  (32*1024)
#define NSTAGE 3
#define GEMM_SMEM (NSTAGE*STAGE)

// ---------------- scratch (device globals; no allocation) ----------------
__device__ __align__(128) __nv_bfloat16 g_Ah[(size_t)MROWS * D_];
__device__ __align__(128) __nv_bfloat16 g_Al[(size_t)MROWS * D_];
__device__ __align__(128) __nv_bfloat16 g_Wth[(size_t)2048 * D_];   // [n][k] KQV bf16 hi
__device__ __align__(128) __nv_bfloat16 g_Wtl[(size_t)2048 * D_];   // [n][k] KQV bf16 lo
__device__ __align__(128) __nv_bfloat16 g_Zh[(size_t)MROWS * ZK];   // token z hi
__device__ __align__(128) __nv_bfloat16 g_Zl[(size_t)MROWS * ZK];   // token z lo
__device__ __align__(128) __nv_bfloat16 g_W2h[(size_t)B_ * 1024 * ZK]; // [b][n][k] hi
__device__ __align__(128) __nv_bfloat16 g_W2l[(size_t)B_ * 1024 * ZK]; // [b][n][k] lo
__device__ float g_K[(size_t)BH_ * T_ * R_];
__device__ float g_V[(size_t)BH_ * T_ * DH_];
__device__ float g_part[(size_t)BH_ * NCH * 4096];
__device__ float g_Tmat[(size_t)BH_ * DH_ * R_];

// ---------------- PTX helpers (baseline ISA only) ----------------
__device__ __forceinline__ uint32_t smem_u32(const void* p) {
    uint32_t a;
    asm("{ .reg .u64 t; cvta.to.shared.u64 t, %1; cvt.u32.u64 %0, t; }" : "=r"(a) : "l"(p));
    return a;
}
__device__ __forceinline__ void cp16(uint32_t dst, const void* src) {
    asm volatile("cp.async.cg.shared.global [%0], [%1], 16;" :: "r"(dst), "l"(src) : "memory");
}
__device__ __forceinline__ void cp_commit() {
    asm volatile("cp.async.commit_group;" ::: "memory");
}
template<int N> __device__ __forceinline__ void cp_wait() {
    asm volatile("cp.async.wait_group %0;" :: "n"(N) : "memory");
}
__device__ __forceinline__ void ldsm4(uint32_t* r, uint32_t addr) {
    asm volatile("ldmatrix.sync.aligned.m8n8.x4.shared.b16 {%0,%1,%2,%3}, [%4];"
                 : "=r"(r[0]), "=r"(r[1]), "=r"(r[2]), "=r"(r[3]) : "r"(addr));
}
__device__ __forceinline__ void mma16816(float* c, const uint32_t* a, const uint32_t* b) {
    asm volatile("mma.sync.aligned.m16n8k16.row.col.f32.bf16.bf16.f32 "
                 "{%0,%1,%2,%3}, {%4,%5,%6,%7}, {%8,%9}, {%0,%1,%2,%3};"
                 : "+f"(c[0]), "+f"(c[1]), "+f"(c[2]), "+f"(c[3])
                 : "r"(a[0]), "r"(a[1]), "r"(a[2]), "r"(a[3]), "r"(b[0]), "r"(b[1]));
}
// 64B-row swizzle
__device__ __forceinline__ uint32_t swz64(uint32_t b) { return b ^ ((b >> 3) & 0x30); }

// ---------------- LayerNorm -> bf16 hi/lo (warp-per-row, barrier-free) ----------------
__global__ __launch_bounds__(256)
void ln_split_kernel(const float* __restrict__ x, const float* __restrict__ sc,
                     const float* __restrict__ bi)
{
    int warp = threadIdx.x >> 5;
    int lane = threadIdx.x & 31;
    int row  = blockIdx.x * 8 + warp;

    const float4* xr = (const float4*)(x + (size_t)row * D_);
    float4 v[8];
    float s = 0.f, ss = 0.f;
    #pragma unroll
    for (int i = 0; i < 8; i++) {
        v[i] = xr[lane + i * 32];
        s  += v[i].x + v[i].y + v[i].z + v[i].w;
        ss += v[i].x*v[i].x + v[i].y*v[i].y + v[i].z*v[i].z + v[i].w*v[i].w;
    }
    #pragma unroll
    for (int o = 16; o > 0; o >>= 1) {
        s  += __shfl_xor_sync(0xffffffffu, s,  o);
        ss += __shfl_xor_sync(0xffffffffu, ss, o);
    }
    float mu   = s  * (1.0f / D_);
    float var  = ss * (1.0f / D_) - mu * mu;
    float rstd = rsqrtf(var + 1e-5f);

    size_t rbase = (size_t)row * D_;
    #pragma unroll
    for (int i = 0; i < 8; i++) {
        int c4 = lane + i * 32;
        float4 s4 = ((const float4*)sc)[c4];
        float4 b4 = ((const float4*)bi)[c4];
        float o0 = (v[i].x - mu) * rstd * s4.x + b4.x;
        float o1 = (v[i].y - mu) * rstd * s4.y + b4.y;
        float o2 = (v[i].z - mu) * rstd * s4.z + b4.z;
        float o3 = (v[i].w - mu) * rstd * s4.w + b4.w;
        size_t base = rbase + (size_t)c4 * 4;
        __nv_bfloat162 h01, h23, l01, l23;
        h01.x = __float2bfloat16(o0); h01.y = __float2bfloat16(o1);
        h23.x = __float2bfloat16(o2); h23.y = __float2bfloat16(o3);
        l01.x = __float2bfloat16(o0 - __bfloat162float(h01.x));
        l01.y = __float2bfloat16(o1 - __bfloat162float(h01.y));
        l23.x = __float2bfloat16(o2 - __bfloat162float(h23.x));
        l23.y = __float2bfloat16(o3 - __bfloat162float(h23.y));
        *(__nv_bfloat162*)(g_Ah + base)     = h01;
        *(__nv_bfloat162*)(g_Ah + base + 2) = h23;
        *(__nv_bfloat162*)(g_Al + base)     = l01;
        *(__nv_bfloat162*)(g_Al + base + 2) = l23;
    }
}

// ---------------- weight transpose + split (Wk/Wq/Wv) ----------------
__global__ __launch_bounds__(256)
void trans_split_kernel(const float* __restrict__ Wk, const float* __restrict__ Wq,
                        const float* __restrict__ Wv)
{
    __shared__ float tile[32][33];
    int z = blockIdx.z;
    const float* W;
    __nv_bfloat16 *dh, *dl;
    int N;
    if (z == 0)      { W = Wk; N = 512;  dh = g_Wth;  dl = g_Wtl; }
    else if (z == 1) { W = Wq; N = 512;  dh = g_Wth + 512 * 1024;  dl = g_Wtl + 512 * 1024; }
    else             { W = Wv; N = 1024; dh = g_Wth + 1024 * 1024; dl = g_Wtl + 1024 * 1024; }
    int n0 = blockIdx.x * 32, k0 = blockIdx.y * 32;
    if (n0 >= N) return;
    int lane = threadIdx.x & 31, wrp = threadIdx.x >> 5;
    for (int i = wrp; i < 32; i += 8)
        tile[i][lane] = W[(size_t)(k0 + i) * N + n0 + lane];
    __syncthreads();
    for (int i = wrp; i < 32; i += 8) {
        float v = tile[lane][i];
        __nv_bfloat16 h = __float2bfloat16(v);
        dh[(size_t)(n0 + i) * D_ + k0 + lane] = h;
        dl[(size_t)(n0 + i) * D_ + k0 + lane] = __float2bfloat16(v - __bfloat162float(h));
    }
}

// ---------------- split-bf16 mma.sync GEMM (templated on mode) ----------------
// MODE 0: A=g_Ah/Al [16384][1024], B=g_Wth/Wtl [2048][1024]
//         skips dead tiles (K & V for t>=P, Q for t<P); epilogue: g_K, g_V, Z
// MODE 1: A=g_Zh/Zl [16384][512],  B=g_W2h/W2l (per-batch), out = sigmoid(gate)*C
template<int MODE>
__global__ __launch_bounds__(256, 2)
void mma_gemm_kernel(float* __restrict__ Cout, const float* __restrict__ gate,
                     const int* __restrict__ pl)
{
    extern __shared__ __align__(1024) char sm[];
    uint32_t sbase = smem_u32(sm);

    const int tid  = threadIdx.x;
    const int lane = tid & 31;
    const int wid  = tid >> 5;
    const int wm   = wid & 3;        // m block (32 rows)
    const int wn   = wid >> 2;       // n block (64 cols)
    const int m0   = blockIdx.y * BM;
    const int ntb  = blockIdx.x * BN;

    int P = *pl; if (P < 1) P = 1; if (P > T_ - 1) P = T_ - 1;

    if (MODE == 0) {
        int t0 = m0 & (T_ - 1);             // BM=128 rows share one batch
        if (ntb < 512) {                    // K region: only t < P read
            if (t0 >= P) return;
        } else if (ntb < 1024) {            // Q region: only t >= P read
            if (t0 + BM - 1 < P) return;
        } else {                            // V region: only t < P read
            if (t0 >= P) return;
        }
    }

    const __nv_bfloat16* Agh;
    const __nv_bfloat16* Agl;
    const __nv_bfloat16* Bgh;
    const __nv_bfloat16* Bgl;
    constexpr int lda = (MODE == 0) ? D_ : ZK;
    constexpr int kch = lda / BK;
    if (MODE == 0) {
        Agh = g_Ah; Agl = g_Al; Bgh = g_Wth; Bgl = g_Wtl;
    } else {
        size_t boff = (size_t)(m0 >> 12) * 1024 * ZK;
        Agh = g_Zh; Agl = g_Zl; Bgh = g_W2h + boff; Bgl = g_W2l + boff;
    }

    float acc[2][8][4];
    #pragma unroll
    for (int i = 0; i < 2; i++)
        #pragma unroll
        for (int j = 0; j < 8; j++)
            #pragma unroll
            for (int k = 0; k < 4; k++) acc[i][j][k] = 0.f;

    const int a_r15 = lane & 15;
    const int a_hi  = lane >> 4;
    const int b_nr  = (lane & 7) | ((lane >> 1) & 8);
    const int b_hi  = (lane >> 3) & 1;

    // loader: 512 16B-units per tensor, 2 per thread
    #define LOAD_STAGE(stg, koff)                                              \
        do {                                                                   \
            _Pragma("unroll")                                                  \
            for (int i_ = 0; i_ < 2; i_++) {                                   \
                int idx_ = tid + i_ * 256;                                     \
                int row_ = idx_ >> 2, u_ = idx_ & 3;                           \
                uint32_t d_ = swz64(row_ * 64 + u_ * 16);                      \
                size_t ka_ = (size_t)(m0 + row_) * lda + (koff) + u_ * 8;      \
                size_t kb_ = (size_t)(ntb + row_) * lda + (koff) + u_ * 8;     \
                cp16((stg) + ST_A_H + d_, Agh + ka_);                          \
                cp16((stg) + ST_A_L + d_, Agl + ka_);                          \
                cp16((stg) + ST_B_H + d_, Bgh + kb_);                          \
                cp16((stg) + ST_B_L + d_, Bgl + kb_);                          \
            }                                                                  \
            cp_commit();                                                       \
        } while (0)

    LOAD_STAGE(sbase, 0);
    LOAD_STAGE(sbase + STAGE, BK);

    int snext = 2;                 // stage receiving prefetch (issued post-sync)
    int scur  = 0;                 // stage being consumed
    for (int c = 0; c < kch; c++) {
        if (c + 1 < kch) cp_wait<1>(); else cp_wait<0>();
        __syncthreads();           // all warps done reading stage snext's old data
        if (c + 2 < kch) LOAD_STAGE(sbase + snext * STAGE, (c + 2) * BK);

        uint32_t st = sbase + scur * STAGE;
        #pragma unroll
        for (int ks = 0; ks < 2; ks++) {
            uint32_t ah0[4], ah1[4], al0[4], al1[4];
            {
                int u = ks * 2 + a_hi;
                uint32_t off0 = swz64((wm * 32 + a_r15) * 64 + u * 16);
                uint32_t off1 = swz64((wm * 32 + 16 + a_r15) * 64 + u * 16);
                ldsm4(ah0, st + ST_A_H + off0);
                ldsm4(ah1, st + ST_A_H + off1);
                ldsm4(al0, st + ST_A_L + off0);
                ldsm4(al1, st + ST_A_L + off1);
            }
            #pragma unroll
            for (int half = 0; half < 2; half++) {
                uint32_t bh[4][2], bl[4][2];
                #pragma unroll
                for (int p = 0; p < 2; p++) {
                    int u = ks * 2 + b_hi;
                    uint32_t off = swz64((wn * 64 + half * 32 + p * 16 + b_nr) * 64 + u * 16);
                    uint32_t r[4];
                    ldsm4(r, st + ST_B_H + off);
                    bh[p*2][0] = r[0]; bh[p*2][1] = r[1];
                    bh[p*2+1][0] = r[2]; bh[p*2+1][1] = r[3];
                    ldsm4(r, st + ST_B_L + off);
                    bl[p*2][0] = r[0]; bl[p*2][1] = r[1];
                    bl[p*2+1][0] = r[2]; bl[p*2+1][1] = r[3];
                }
                #pragma unroll
                for (int f = 0; f < 4; f++) {
                    int nf = half * 4 + f;
                    mma16816(acc[0][nf], ah0, bh[f]);
                    mma16816(acc[1][nf], ah1, bh[f]);
                    mma16816(acc[0][nf], ah0, bl[f]);
                    mma16816(acc[1][nf], ah1, bl[f]);
                    mma16816(acc[0][nf], al0, bh[f]);
                    mma16816(acc[1][nf], al1, bh[f]);
                }
            }
        }
        scur  = (scur == NSTAGE - 1) ? 0 : scur + 1;
        snext = (snext == NSTAGE - 1) ? 0 : snext + 1;
    }

    // ---- epilogue ----
    float gm = (MODE == 1) ? (1.0f / (1.0f + expf(-gate[0]))) : 1.0f;
    #pragma unroll
    for (int mf = 0; mf < 2; mf++) {
        int mrow0 = m0 + wm * 32 + mf * 16 + (lane >> 2);
        #pragma unroll
        for (int nf = 0; nf < 8; nf++) {
            int n = ntb + wn * 64 + nf * 8 + (lane & 3) * 2;
            #pragma unroll
            for (int rh = 0; rh < 2; rh++) {
                int m = mrow0 + rh * 8;
                float2 v;
                v.x = gm * acc[mf][nf][rh * 2 + 0];
                v.y = gm * acc[mf][nf][rh * 2 + 1];
                if (MODE == 1) {
                    *(float2*)(Cout + (size_t)m * 1024 + n) = v;
                } else {
                    int b = m >> 12, t = m & (T_ - 1);
                    if (n < 1024) {
                        int zc = (n < 512) ? n : (n - 512);
                        bool emit = (n < 512) ? (t < P) : (t >= P);
                        if (emit) {
                            __nv_bfloat162 hv, lv;
                            hv.x = __float2bfloat16(v.x);
                            hv.y = __float2bfloat16(v.y);
                            lv.x = __float2bfloat16(v.x - __bfloat162float(hv.x));
                            lv.y = __float2bfloat16(v.y - __bfloat162float(hv.y));
                            *(__nv_bfloat162*)(g_Zh + (size_t)m * ZK + zc) = hv;
                            *(__nv_bfloat162*)(g_Zl + (size_t)m * ZK + zc) = lv;
                        }
                        if (n < 512) {
                            float* dst = g_K + (((size_t)(b * H_ + (n >> 5))) * T_ + t) * R_ + (n & 31);
                            *(float2*)dst = v;
                        }
                    } else {
                        int nv = n - 1024;
                        float* dst = g_V + (((size_t)(b * H_ + (nv >> 6))) * T_ + t) * DH_ + (nv & 63);
                        *(float2*)dst = v;
                    }
                }
            }
        }
    }
}

// ---------------- partial G/M/Cv accumulation (R13 float4 shape) ----------------
__global__ __launch_bounds__(256)
void build_partial_kernel(const int* __restrict__ pl)
{
    int bh = blockIdx.x;
    int chunk = blockIdx.y;
    int P = *pl; if (P < 1) P = 1; if (P > T_ - 1) P = T_ - 1;
    int ch = (P + NCH - 1) / NCH;
    int lo = chunk * ch;
    int hi = min(lo + ch, P);
    int Pm1 = P - 1;

    const float* K = g_K + (size_t)bh * T_ * R_;
    const float* V = g_V + (size_t)bh * T_ * DH_;
    __shared__ __align__(16) float Ks[65][32];
    __shared__ __align__(16) float Vs[64][64];

    int tid = threadIdx.x;
    int r = tid & 31, g = tid >> 5;
    float4 gacc = {0, 0, 0, 0};
    float4 macc = {0, 0, 0, 0};
    float4 ca   = {0, 0, 0, 0};
    float4 cb   = {0, 0, 0, 0};

    for (int t0 = lo; t0 < hi; t0 += 64) {
        int nrows = min(64, hi - t0);
        for (int idx = tid; idx < (nrows + 1) * 8; idx += 256) {
            int rr = idx >> 3, cq = (idx & 7) * 4;
            *(float4*)&Ks[rr][cq] = *(const float4*)&K[(size_t)(t0 + rr) * R_ + cq];
        }
        for (int idx = tid; idx < nrows * 16; idx += 256) {
            int rr = idx >> 4, cq = (idx & 15) * 4;
            *(float4*)&Vs[rr][cq] = *(const float4*)&V[(size_t)(t0 + rr) * DH_ + cq];
        }
        __syncthreads();
        #pragma unroll 4
        for (int tt = 0; tt < nrows; tt++) {
            float kr = Ks[tt][r];
            float kn = (t0 + tt < Pm1) ? Ks[tt + 1][r] : 0.f;
            float4 ks = *(const float4*)&Ks[tt][g * 4];
            float4 va = *(const float4*)&Vs[tt][g * 8];
            float4 vb = *(const float4*)&Vs[tt][g * 8 + 4];
            gacc.x += kr * ks.x; gacc.y += kr * ks.y;
            gacc.z += kr * ks.z; gacc.w += kr * ks.w;
            macc.x += kn * ks.x; macc.y += kn * ks.y;
            macc.z += kn * ks.z; macc.w += kn * ks.w;
            ca.x += kr * va.x; ca.y += kr * va.y;
            ca.z += kr * va.z; ca.w += kr * va.w;
            cb.x += kr * vb.x; cb.y += kr * vb.y;
            cb.z += kr * vb.z; cb.w += kr * vb.w;
        }
        __syncthreads();
    }
    float* out = g_part + ((size_t)bh * NCH + chunk) * 4096;
    out[r * 32 + g * 4 + 0] = gacc.x;  out[r * 32 + g * 4 + 1] = gacc.y;
    out[r * 32 + g * 4 + 2] = gacc.z;  out[r * 32 + g * 4 + 3] = gacc.w;
    out[1024 + r * 32 + g * 4 + 0] = macc.x;  out[1024 + r * 32 + g * 4 + 1] = macc.y;
    out[1024 + r * 32 + g * 4 + 2] = macc.z;  out[1024 + r * 32 + g * 4 + 3] = macc.w;
    #pragma unroll
    for (int j = 0; j < 4; j++) {
        out[2048 + (g * 8 + j) * 32 + r]     = (&ca.x)[j];
        out[2048 + (g * 8 + 4 + j) * 32 + r] = (&cb.x)[j];
    }
}

// ---------------- per-head solve ----------------
#define MM32(Cm, Am, Bm)                                                     \
    do {                                                                     \
        for (int e = tid; e < 1024; e += 256) {                              \
            int rr = e >> 5, cc = e & 31; float s = 0.f;                     \
            _Pragma("unroll") for (int k2 = 0; k2 < 32; k2++)                \
                s += Am[rr][k2] * Bm[k2][cc];                                \
            Cm[rr][cc] = s;                                                  \
        }                                                                    \
        __syncthreads();                                                     \
    } while (0)

__global__ __launch_bounds__(256)
void solve_kernel(const float* __restrict__ lridge, const float* __restrict__ lgamma)
{
    __shared__ float sG[32][33], sM[32][33], sL[32][33], sLi[32][33];
    __shared__ float sAw[32][33], sT[32][33];
    __shared__ float sCv[64][33], sBv[64][33];
    __shared__ float sScale;

    int bh = blockIdx.x;
    int tid = threadIdx.x;

    // float4 reduce of NCH partials
    const float* base = g_part + (size_t)bh * NCH * 4096;
    for (int idx4 = tid; idx4 < 1024; idx4 += 256) {
        float4 s = {0.f, 0.f, 0.f, 0.f};
        #pragma unroll
        for (int c = 0; c < NCH; c++) {
            float4 p = *(const float4*)&base[(size_t)c * 4096 + idx4 * 4];
            s.x += p.x; s.y += p.y; s.z += p.z; s.w += p.w;
        }
        int idx = idx4 * 4;
        #pragma unroll
        for (int j = 0; j < 4; j++) {
            float sv = (&s.x)[j];
            int e = idx + j;
            if (e < 1024)      sG[e >> 5][e & 31] = sv;
            else if (e < 2048) sM[(e - 1024) >> 5][e & 31] = sv;
            else { int e2 = e - 2048; sCv[e2 >> 5][e2 & 31] = sv; }
        }
    }
    __syncthreads();
    if (tid < 32) sG[tid][tid] += expf(lridge[0]);
    __syncthreads();

    if (tid < 32) {
        int i = tid;
        for (int j = 0; j < 32; j++) {
            if (i == j) {
                float s = sG[j][j];
                for (int k = 0; k < j; k++) s -= sL[j][k] * sL[j][k];
                sL[j][j] = sqrtf(fmaxf(s, 1e-30f));
            }
            __syncwarp();
            if (i > j) {
                float s = sG[i][j];
                for (int k = 0; k < j; k++) s -= sL[i][k] * sL[j][k];
                sL[i][j] = s / sL[j][j];
            } else if (i < j) {
                sL[i][j] = 0.f;
            }
            __syncwarp();
        }
        int j = tid;
        for (int i2 = 0; i2 < 32; i2++) sLi[i2][j] = 0.f;
        for (int i2 = j; i2 < 32; i2++) {
            float s = (i2 == j) ? 1.f : 0.f;
            for (int k = j; k < i2; k++) s -= sL[i2][k] * sLi[k][j];
            sLi[i2][j] = s / sL[i2][i2];
        }
    }
    __syncthreads();

    MM32(sT, sLi, sM);
    for (int e = tid; e < 1024; e += 256) {
        int rr = e >> 5, cc = e & 31; float s = 0.f;
        #pragma unroll
        for (int k2 = 0; k2 < 32; k2++) s += sT[rr][k2] * sLi[cc][k2];
        sAw[rr][cc] = s;
    }
    __syncthreads();

    if (tid < 32) {
        int i = tid;
        float v = 1.0f + 0.37f * (float)i;
        float sig = 0.f;
        for (int it = 0; it < 64; it++) {
            float u = 0.f;
            #pragma unroll
            for (int k = 0; k < 32; k++) u += sAw[i][k] * __shfl_sync(0xffffffffu, v, k);
            float w = 0.f;
            #pragma unroll
            for (int k = 0; k < 32; k++) w += sAw[k][i] * __shfl_sync(0xffffffffu, u, k);
            float n2 = w * w;
            #pragma unroll
            for (int o = 16; o > 0; o >>= 1) n2 += __shfl_xor_sync(0xffffffffu, n2, o);
            float nrm = sqrtf(n2);
            v = w / fmaxf(nrm, 1e-30f);
            sig = sqrtf(nrm);
        }
        if (i == 0) {
            float gamma = expf(lgamma[0]);
            float gc = fminf(gamma, 1.0f);
            float s0 = fmaxf(sig, 1e-8f);
            sScale = gc / fmaxf(s0, 1.0f);
        }
    }
    __syncthreads();
    float scl = sScale;
    for (int e = tid; e < 1024; e += 256) sAw[e >> 5][e & 31] *= scl;
    __syncthreads();

    MM32(sT, sAw, sAw);
    MM32(sM, sT, sT);
    MM32(sG, sM, sLi);
    MM32(sT, sL, sG);

    for (int e = tid; e < 2048; e += 256) {
        int dd = e >> 5, rr = e & 31; float s = 0.f;
        #pragma unroll
        for (int k2 = 0; k2 < 32; k2++) s += sCv[dd][k2] * sLi[rr][k2];
        sBv[dd][rr] = s;
    }
    __syncthreads();
    for (int e = tid; e < 2048; e += 256) {
        int dd = e >> 5, rr = e & 31; float s = 0.f;
        #pragma unroll
        for (int k2 = 0; k2 < 32; k2++) s += sBv[dd][k2] * sLi[k2][rr];
        sCv[dd][rr] = s;
    }
    __syncthreads();

    float* tm = g_Tmat + (size_t)bh * DH_ * R_;
    for (int e = tid; e < 2048; e += 256) {
        int dd = e >> 5, rr = e & 31; float s = 0.f;
        #pragma unroll
        for (int k2 = 0; k2 < 32; k2++) s += sCv[dd][k2] * sT[k2][rr];
        tm[dd * R_ + rr] = s;
    }
}

// ---------------- W2_b[n][h*32+r] = sum_d Tmat_bh[d][r] * Wo[h*64+d][n] (fp32 Wo) ----------------
__global__ __launch_bounds__(256)
void w2_kernel(const float* __restrict__ Wo)
{
    int bh = blockIdx.x;            // b*16+h
    int h  = bh & 15;
    int b  = bh >> 4;
    int n  = blockIdx.y * 256 + threadIdx.x;   // output column 0..1023

    __shared__ float Tm[DH_][R_ + 1];
    for (int i = threadIdx.x; i < DH_ * R_; i += 256)
        Tm[i >> 5][i & 31] = g_Tmat[(size_t)bh * DH_ * R_ + i];
    __syncthreads();

    float s[R_];
    #pragma unroll
    for (int r = 0; r < R_; r++) s[r] = 0.f;
    for (int d = 0; d < DH_; d++) {
        float w = Wo[(size_t)(h * DH_ + d) * 1024 + n];   // coalesced over n
        #pragma unroll
        for (int r = 0; r < R_; r++) s[r] += Tm[d][r] * w;
    }
    size_t base = ((size_t)b * 1024 + n) * ZK + h * R_;
    #pragma unroll
    for (int r = 0; r < R_; r++) {
        __nv_bfloat16 hv = __float2bfloat16(s[r]);
        g_W2h[base + r] = hv;
        g_W2l[base + r] = __float2bfloat16(s[r] - __bfloat162float(hv));
    }
}

// ---------------- launcher ----------------
extern "C" void kernel_launch(void* const* d_in, const int* in_sizes, int n_in,
                              void* d_out, int out_size)
{
    const float* hs     = (const float*)d_in[0];
    const float* Wk     = (const float*)d_in[1];
    const float* Wq     = (const float*)d_in[2];
    const float* Wv     = (const float*)d_in[3];
    const float* Wo     = (const float*)d_in[4];
    const float* lns    = (const float*)d_in[5];
    const float* lnb    = (const float*)d_in[6];
    const float* gate   = (const float*)d_in[7];
    const float* lridge = (const float*)d_in[8];
    const float* lgamma = (const float*)d_in[9];
    const int*   pl     = (const int*)d_in[10];
    float* out = (float*)d_out;

    cudaFuncSetAttribute(mma_gemm_kernel<0>,
                         cudaFuncAttributeMaxDynamicSharedMemorySize, GEMM_SMEM);
    cudaFuncSetAttribute(mma_gemm_kernel<1>,
                         cudaFuncAttributeMaxDynamicSharedMemorySize, GEMM_SMEM);

    ln_split_kernel<<<MROWS / 8, 256>>>(hs, lns, lnb);

    trans_split_kernel<<<dim3(32, 32, 3), 256>>>(Wk, Wq, Wv);

    mma_gemm_kernel<0><<<dim3(2048 / BN, MROWS / BM), 256, GEMM_SMEM>>>(nullptr, nullptr, pl);

    build_partial_kernel<<<dim3(BH_, NCH), 256>>>(pl);
    solve_kernel<<<BH_, 256>>>(lridge, lgamma);
    w2_kernel<<<dim3(BH_, 4), 256>>>(Wo);

    mma_gemm_kernel<1><<<dim3(1024 / BN, MROWS / BM), 256, GEMM_SMEM>>>(out, gate, pl);
}